// round 8
// baseline (speedup 1.0000x reference)
#include <cuda_runtime.h>
#include <cuda_fp16.h>
#include <math.h>
#include <stdint.h>

// Problem constants
#define Bb   4
#define Cc   64
#define Hh   96
#define Ww   96
#define HW   (Hh*Ww)            // 9216
#define Oo   64
#define CIN3 (3*Cc)             // 192
#define IMG  (Cc*HW)            // 589824
#define NPIX (Bb*HW)            // 36864
#define NCH  27                 // K chunks of 64: K = k*192 + c (k-major)

// Scratch
__device__ float  g_x[Bb * HW * CIN3];   // NHWC packed (ref|dist|diff)
__device__ float4 g_mw[Bb * 9 * HW];
__device__ int4   g_mi[Bb * 9 * HW];     // NHWC element offsets (pix*192)
__device__ __half g_wh[NCH * 64 * 64];   // B tiles fp16 (pre-swizzled)

// ---------------- helpers ----------------
__device__ __forceinline__ uint32_t smem_to_u32(const void* p) {
    uint32_t a;
    asm("{ .reg .u64 t; cvta.to.shared.u64 t, %1; cvt.u32.u64 %0, t; }"
        : "=r"(a) : "l"(p));
    return a;
}
__device__ __forceinline__ void ldsm_x4(uint32_t* r, uint32_t addr) {
    asm volatile("ldmatrix.sync.aligned.m8n8.x4.shared.b16 {%0,%1,%2,%3}, [%4];"
        : "=r"(r[0]), "=r"(r[1]), "=r"(r[2]), "=r"(r[3]) : "r"(addr));
}
__device__ __forceinline__ void mma_f16(float* d, const uint32_t* a,
                                        uint32_t b0, uint32_t b1) {
    asm volatile("mma.sync.aligned.m16n8k16.row.col.f32.f16.f16.f32 "
        "{%0,%1,%2,%3}, {%4,%5,%6,%7}, {%8,%9}, {%0,%1,%2,%3};"
        : "+f"(d[0]), "+f"(d[1]), "+f"(d[2]), "+f"(d[3])
        : "r"(a[0]), "r"(a[1]), "r"(a[2]), "r"(a[3]), "r"(b0), "r"(b1));
}
__device__ __forceinline__ void cp_async16(uint32_t smem_addr, const void* gptr) {
    asm volatile("cp.async.cg.shared.global [%0], [%1], 16;"
        :: "r"(smem_addr), "l"(gptr));
}
#define CP_COMMIT() asm volatile("cp.async.commit_group;" ::: "memory")
#define CP_WAIT0()  asm volatile("cp.async.wait_group 0;" ::: "memory")

// ---------------------------------------------------------------------------
// Prolog (block-range dispatch, 256 threads):
//   [0,144):      offset conv3x3 + fused bilinear meta (256 px/block)
//   [144,1296):   diff + NHWC repack (32-px tiles)
//   [1296,1392):  weight prep -> fp16 B tiles, XOR-swizzled [n][k]
// ---------------------------------------------------------------------------
__global__ __launch_bounds__(256) void prolog_kernel(
        const float* __restrict__ ref, const float* __restrict__ dist,
        const float* __restrict__ ow, const float* __restrict__ ob,
        const float* __restrict__ dw,
        float* __restrict__ out_diff, float* __restrict__ xpk,
        float4* __restrict__ mw, int4* __restrict__ mi,
        __half* __restrict__ wh) {
    __shared__ __align__(16) float s_buf[576 * 20];   // 46KB, shared by paths
    int tid = threadIdx.x;
    int bid = blockIdx.x;

    if (bid >= 1296) {
        // ---- wprep ----
        for (int i = (bid - 1296) * 256 + tid; i < NCH * 64 * 64; i += 96 * 256) {
            int c  = i & 63;
            int o  = (i >> 6) & 63;
            int ch = i >> 12;
            int k  = ch / 3;
            int cg = (ch % 3) * 64 + c;
            float v = __ldg(dw + o * (CIN3 * 9) + cg * 9 + k);
            int elem = o * 64 + (((c >> 3) ^ (o & 7)) << 3) + (c & 7);
            wh[ch * 4096 + elem] = __float2half_rn(v);
        }
        return;
    }
    if (bid >= 144) {
        // ---- diff + NHWC repack: 32-px tile ----
        float (*t)[33] = (float(*)[33])s_buf;
        int rb   = bid - 144;
        int b    = rb / 288;
        int pix0 = (rb % 288) * 32;
        for (int i = tid; i < CIN3 * 32; i += 256) {
            int c = i >> 5, p = i & 31;
            int pix = pix0 + p;
            float v;
            if (c < Cc) {
                v = __ldg(ref + b * IMG + c * HW + pix);
            } else if (c < 2 * Cc) {
                v = __ldg(dist + b * IMG + (c - Cc) * HW + pix);
            } else {
                int cc = c - 2 * Cc;
                float r = __ldg(ref  + b * IMG + cc * HW + pix);
                float d = __ldg(dist + b * IMG + cc * HW + pix);
                v = (r - d) * (r - d);
                out_diff[b * IMG + cc * HW + pix] = v;
            }
            t[c][p] = v;
        }
        __syncthreads();
        for (int i = tid; i < 32 * 48; i += 256) {
            int p = i / 48, c4 = i % 48;
            int c = c4 * 4;
            float4 v = make_float4(t[c][p], t[c + 1][p], t[c + 2][p], t[c + 3][p]);
            ((float4*)(xpk + (size_t)(b * HW + pix0 + p) * CIN3))[c4] = v;
        }
        return;
    }

    // ---- offset conv + meta (256 px/block) ----
    float* s_w = s_buf;
    for (int i = tid; i < 18 * 576; i += 256) {
        int o = i / 576, ck = i % 576;
        s_w[ck * 20 + o] = ow[i];
    }
    __syncthreads();

    int p = bid * 256 + tid;
    int b = p / HW;
    int pix = p % HW;
    int y = pix / Ww, x = pix % Ww;

    int  idx9[9]; bool ok9[9];
#pragma unroll
    for (int ky = 0; ky < 3; ky++)
#pragma unroll
        for (int kx = 0; kx < 3; kx++) {
            int yy = y + ky - 1, xx = x + kx - 1;
            bool ok = (yy >= 0) && (yy < Hh) && (xx >= 0) && (xx < Ww);
            ok9[ky * 3 + kx] = ok;
            idx9[ky * 3 + kx] = (ok ? yy : 0) * Ww + (ok ? xx : 0);
        }

    float acc[18];
#pragma unroll
    for (int o = 0; o < 18; o++) acc[o] = 0.f;

    const float* xb = ref + b * IMG;
    for (int c = 0; c < Cc; c++) {
        const float* xc = xb + c * HW;
#pragma unroll
        for (int k = 0; k < 9; k++) {
            float v = ok9[k] ? __ldg(xc + idx9[k]) : 0.f;
            int base = (c * 9 + k) * 20;
            float4 w0 = *(const float4*)&s_w[base];
            float4 w1 = *(const float4*)&s_w[base + 4];
            float4 w2 = *(const float4*)&s_w[base + 8];
            float4 w3 = *(const float4*)&s_w[base + 12];
            float  wa = s_w[base + 16];
            float  wb = s_w[base + 17];
            acc[0]  += v * w0.x;  acc[1]  += v * w0.y;  acc[2]  += v * w0.z;  acc[3]  += v * w0.w;
            acc[4]  += v * w1.x;  acc[5]  += v * w1.y;  acc[6]  += v * w1.z;  acc[7]  += v * w1.w;
            acc[8]  += v * w2.x;  acc[9]  += v * w2.y;  acc[10] += v * w2.z;  acc[11] += v * w2.w;
            acc[12] += v * w3.x;  acc[13] += v * w3.y;  acc[14] += v * w3.z;  acc[15] += v * w3.w;
            acc[16] += v * wa;    acc[17] += v * wb;
        }
    }

#pragma unroll
    for (int k = 0; k < 9; k++) {
        float offy = acc[2 * k]     + __ldg(ob + 2 * k);
        float offx = acc[2 * k + 1] + __ldg(ob + 2 * k + 1);
        float py = (float)(y - 1 + k / 3) + offy;
        float px = (float)(x - 1 + k % 3) + offx;
        float fy = floorf(py), fx = floorf(px);
        int y0 = (int)fy, x0 = (int)fx;
        float dy = py - fy, dx = px - fx;
        float wv[4]; int iv[4];
#pragma unroll
        for (int t = 0; t < 4; t++) {
            int yt = y0 + (t >> 1);
            int xt = x0 + (t & 1);
            float wt = ((t >> 1) ? dy : (1.f - dy)) * ((t & 1) ? dx : (1.f - dx));
            bool valid = (yt >= 0) && (yt < Hh) && (xt >= 0) && (xt < Ww);
            int yc = yt < 0 ? 0 : (yt > Hh - 1 ? Hh - 1 : yt);
            int xc = xt < 0 ? 0 : (xt > Ww - 1 ? Ww - 1 : xt);
            wv[t] = valid ? wt : 0.f;
            iv[t] = (yc * Ww + xc) * CIN3;   // NHWC element offset
        }
        int mo = (b * 9 + k) * HW + pix;
        mw[mo] = make_float4(wv[0], wv[1], wv[2], wv[3]);
        mi[mo] = make_int4(iv[0], iv[1], iv[2], iv[3]);
    }
}

// ---------------------------------------------------------------------------
// Deformable conv: mma.sync fp16 (A_hi + A_lo) x B_hi, double-buffered.
// NHWC gather: warp owns 16 px/chunk; per pixel 2x LDG.128 (4ch x 2 taps per
// half-warp) + shfl_xor(16) tap-combine.
// Per buffer (40KB): A_hi@0 16K | A_lo@16K 16K | B_hi@32K 8K
// ---------------------------------------------------------------------------
#define SM_BUF   40960
#define SM_AHOF  0
#define SM_ALOF  16384
#define SM_BHOF  32768
#define SM_TOTAL (2 * SM_BUF)

__global__ __launch_bounds__(256, 2) void deform_kernel(
        const float* __restrict__ xpk,
        const float4* __restrict__ mw, const int4* __restrict__ mi,
        const __half* __restrict__ wh,
        const float* __restrict__ db, float* __restrict__ out) {
    extern __shared__ char smem[];
    uint32_t sb = smem_to_u32(smem);

    int tid  = threadIdx.x;
    int lane = tid & 31;
    int warp = tid >> 5;
    int b    = blockIdx.x / 72;
    int pix0 = (blockIdx.x % 72) * 128;

    int m0 = (warp & 3) * 32;
    int n0 = (warp >> 2) * 32;

    const float* xb = xpk + (size_t)b * HW * CIN3;

    float acc[2][4][4];
#pragma unroll
    for (int i = 0; i < 2; i++)
#pragma unroll
        for (int j = 0; j < 4; j++)
#pragma unroll
            for (int q = 0; q < 4; q++) acc[i][j][q] = 0.f;

    uint32_t a_m  = lane & 15;
    uint32_t a_kc = lane >> 4;
    uint32_t b_n  = ((lane >> 4) << 3) + (lane & 7);
    uint32_t b_kc = (lane >> 3) & 1;

    int bcp0 = tid, bcp1 = tid + 256;

    // gather lane roles
    int lh = lane >> 4;     // 0: taps (x,z); 1: taps (y,w)
    int c4 = lane & 15;     // channel quad

    // build 4 pixels (quarter q) of chunk ch
    auto build_q = [&](int ch, int q) {
        int k   = ch / 3;
        int cbl = ch - 3 * k;
        const float* xp = xb + cbl * 64;
        char* bufc = smem + (ch & 1) * SM_BUF;
        const float4* mwb = mw + (b * 9 + k) * HW + pix0;
        const int4*   mib = mi + (b * 9 + k) * HW + pix0;
#pragma unroll
        for (int j = 0; j < 4; j++) {
            int p = warp * 16 + q * 4 + j;
            float4 wgt = __ldg(mwb + p);
            int4   idx = __ldg(mib + p);
            int   i1 = lh ? idx.y : idx.x;
            int   i2 = lh ? idx.w : idx.z;
            float w1 = lh ? wgt.y : wgt.x;
            float w2 = lh ? wgt.w : wgt.z;
            float4 a1 = __ldg((const float4*)(xp + i1) + c4);
            float4 a2 = __ldg((const float4*)(xp + i2) + c4);
            float4 pa;
            pa.x = a1.x * w1 + a2.x * w2;
            pa.y = a1.y * w1 + a2.y * w2;
            pa.z = a1.z * w1 + a2.z * w2;
            pa.w = a1.w * w1 + a2.w * w2;
            float v0 = pa.x + __shfl_xor_sync(0xFFFFFFFFu, pa.x, 16);
            float v1 = pa.y + __shfl_xor_sync(0xFFFFFFFFu, pa.y, 16);
            float v2 = pa.z + __shfl_xor_sync(0xFFFFFFFFu, pa.z, 16);
            float v3 = pa.w + __shfl_xor_sync(0xFFFFFFFFu, pa.w, 16);
            if (lane < 16) {
                __half h0 = __float2half_rn(v0), h1 = __float2half_rn(v1);
                __half h2 = __float2half_rn(v2), h3 = __float2half_rn(v3);
                __half2 hi01 = __halves2half2(h0, h1);
                __half2 hi23 = __halves2half2(h2, h3);
                __half2 lo01 = __halves2half2(
                    __float2half_rn(v0 - __half2float(h0)),
                    __float2half_rn(v1 - __half2float(h1)));
                __half2 lo23 = __halves2half2(
                    __float2half_rn(v2 - __half2float(h2)),
                    __float2half_rn(v3 - __half2float(h3)));
                uint32_t off = (uint32_t)p * 128
                             + (uint32_t)((((c4 >> 1) ^ (p & 7)) << 4) + ((c4 & 1) << 3));
                *(uint2*)(bufc + SM_AHOF + off) =
                    make_uint2(*(uint32_t*)&hi01, *(uint32_t*)&hi23);
                *(uint2*)(bufc + SM_ALOF + off) =
                    make_uint2(*(uint32_t*)&lo01, *(uint32_t*)&lo23);
            }
        }
    };

    auto stage_B = [&](int ch) {
        uint32_t bufb = sb + (ch & 1) * SM_BUF;
        const char* gh = (const char*)(wh + ch * 4096);
        cp_async16(bufb + SM_BHOF + bcp0 * 16, gh + bcp0 * 16);
        cp_async16(bufb + SM_BHOF + bcp1 * 16, gh + bcp1 * 16);
        CP_COMMIT();
    };

    // prologue: chunk 0
    stage_B(0);
#pragma unroll
    for (int q = 0; q < 4; q++) build_q(0, q);
    CP_WAIT0();
    __syncthreads();

    for (int ch = 0; ch < NCH; ch++) {
        int nxt = ch + 1;
        bool has_nxt = (nxt < NCH);
        if (has_nxt) stage_B(nxt);

        uint32_t bufb = sb + (ch & 1) * SM_BUF;
#pragma unroll
        for (int ks = 0; ks < 4; ks++) {
            uint32_t ah[2][4], al[2][4], bh[2][4];
#pragma unroll
            for (int mi_ = 0; mi_ < 2; mi_++) {
                uint32_t row = m0 + mi_ * 16 + a_m;
                uint32_t aoff = row * 128 + ((((ks << 1) + a_kc) ^ (row & 7)) << 4);
                ldsm_x4(ah[mi_], bufb + SM_AHOF + aoff);
                ldsm_x4(al[mi_], bufb + SM_ALOF + aoff);
            }
#pragma unroll
            for (int g = 0; g < 2; g++) {
                uint32_t n  = n0 + g * 16 + b_n;
                uint32_t kc = (ks << 1) + b_kc;
                uint32_t boff = n * 128 + ((kc ^ (n & 7)) << 4);
                ldsm_x4(bh[g], bufb + SM_BHOF + boff);
            }
#pragma unroll
            for (int mi_ = 0; mi_ < 2; mi_++)
#pragma unroll
                for (int g = 0; g < 2; g++)
#pragma unroll
                    for (int s = 0; s < 2; s++) {
                        int ni = g * 2 + s;
                        mma_f16(acc[mi_][ni], ah[mi_], bh[g][2 * s], bh[g][2 * s + 1]);
                        mma_f16(acc[mi_][ni], al[mi_], bh[g][2 * s], bh[g][2 * s + 1]);
                    }
            if (has_nxt) build_q(nxt, ks);
        }

        CP_WAIT0();
        __syncthreads();
    }

    // epilogue: bias + relu
    int r  = lane >> 2;
    int cp = (lane & 3) * 2;
#pragma unroll
    for (int mi_ = 0; mi_ < 2; mi_++) {
        int pixb = pix0 + m0 + mi_ * 16 + r;
#pragma unroll
        for (int ni = 0; ni < 4; ni++) {
            int o = n0 + ni * 8 + cp;
            float b0v = __ldg(db + o);
            float b1v = __ldg(db + o + 1);
            float* o0 = out + (size_t)(b * Oo + o) * HW;
            float* o1 = out + (size_t)(b * Oo + o + 1) * HW;
            float v;
            v = acc[mi_][ni][0] + b0v; o0[pixb]     = v > 0.f ? v : 0.f;
            v = acc[mi_][ni][1] + b1v; o1[pixb]     = v > 0.f ? v : 0.f;
            v = acc[mi_][ni][2] + b0v; o0[pixb + 8] = v > 0.f ? v : 0.f;
            v = acc[mi_][ni][3] + b1v; o1[pixb + 8] = v > 0.f ? v : 0.f;
        }
    }
}

// ---------------------------------------------------------------------------
extern "C" void kernel_launch(void* const* d_in, const int* in_sizes, int n_in,
                              void* d_out, int out_size) {
    const float* ref  = (const float*)d_in[0];
    const float* dist = (const float*)d_in[1];
    const float* ow   = (const float*)d_in[2];
    const float* ob   = (const float*)d_in[3];
    const float* dw   = (const float*)d_in[4];
    const float* db   = (const float*)d_in[5];
    float* out = (float*)d_out;
    float* out_feat = out;
    float* out_diff = out + Bb * IMG;

    float*  xpk; cudaGetSymbolAddress((void**)&xpk, g_x);
    float4* mw;  cudaGetSymbolAddress((void**)&mw, g_mw);
    int4*   mi;  cudaGetSymbolAddress((void**)&mi, g_mi);
    __half* wh;  cudaGetSymbolAddress((void**)&wh, g_wh);

    cudaFuncSetAttribute(deform_kernel,
                         cudaFuncAttributeMaxDynamicSharedMemorySize, SM_TOTAL);

    prolog_kernel<<<1392, 256>>>(ref, dist, ow, ob, dw, out_diff, xpk, mw, mi, wh);
    deform_kernel<<<NPIX / 128, 256, SM_TOTAL>>>(xpk, mw, mi, wh, db, out_feat);
}

// round 9
// speedup vs baseline: 1.3539x; 1.3539x over previous
#include <cuda_runtime.h>
#include <cuda_fp16.h>
#include <math.h>
#include <stdint.h>

// Problem constants
#define Bb   4
#define Cc   64
#define Hh   96
#define Ww   96
#define HW   (Hh*Ww)            // 9216
#define Oo   64
#define CIN3 (3*Cc)             // 192
#define IMG  (Cc*HW)            // 589824
#define NPIX (Bb*HW)            // 36864
#define NCH  27                 // K chunks of 64: K = k*192 + c (k-major)

// Scratch
__device__ float4 g_mw[Bb * 9 * HW];
__device__ int4   g_mi[Bb * 9 * HW];
__device__ __half g_wh[NCH * 64 * 64];   // B tiles fp16 (pre-swizzled)

// ---------------- helpers ----------------
__device__ __forceinline__ uint32_t smem_to_u32(const void* p) {
    uint32_t a;
    asm("{ .reg .u64 t; cvta.to.shared.u64 t, %1; cvt.u32.u64 %0, t; }"
        : "=r"(a) : "l"(p));
    return a;
}
__device__ __forceinline__ void ldsm_x4(uint32_t* r, uint32_t addr) {
    asm volatile("ldmatrix.sync.aligned.m8n8.x4.shared.b16 {%0,%1,%2,%3}, [%4];"
        : "=r"(r[0]), "=r"(r[1]), "=r"(r[2]), "=r"(r[3]) : "r"(addr));
}
__device__ __forceinline__ void mma_f16(float* d, const uint32_t* a,
                                        uint32_t b0, uint32_t b1) {
    asm volatile("mma.sync.aligned.m16n8k16.row.col.f32.f16.f16.f32 "
        "{%0,%1,%2,%3}, {%4,%5,%6,%7}, {%8,%9}, {%0,%1,%2,%3};"
        : "+f"(d[0]), "+f"(d[1]), "+f"(d[2]), "+f"(d[3])
        : "r"(a[0]), "r"(a[1]), "r"(a[2]), "r"(a[3]), "r"(b0), "r"(b1));
}
__device__ __forceinline__ void cp_async16(uint32_t smem_addr, const void* gptr) {
    asm volatile("cp.async.cg.shared.global [%0], [%1], 16;"
        :: "r"(smem_addr), "l"(gptr));
}
#define CP_COMMIT() asm volatile("cp.async.commit_group;" ::: "memory")
#define CP_WAIT0()  asm volatile("cp.async.wait_group 0;" ::: "memory")

// ---------------------------------------------------------------------------
// Kernel 1: diff = (ref - dist)^2
// ---------------------------------------------------------------------------
__global__ void diff_kernel(const float* __restrict__ ref,
                            const float* __restrict__ dist,
                            float* __restrict__ out_diff) {
    int i = blockIdx.x * blockDim.x + threadIdx.x;
    if (i < Bb * IMG) {
        float d = ref[i] - dist[i];
        out_diff[i] = d * d;
    }
}

// ---------------------------------------------------------------------------
// Kernel 2: offset conv3x3 (Cin=64 -> 18) + fused bilinear meta (R6 version)
// ---------------------------------------------------------------------------
__global__ __launch_bounds__(128) void offset_meta_kernel(
        const float* __restrict__ ref,
        const float* __restrict__ ow, const float* __restrict__ ob,
        float4* __restrict__ mw, int4* __restrict__ mi) {
    __shared__ __align__(16) float s_w[576 * 20];
    int tid = threadIdx.x;
    for (int i = tid; i < 18 * 576; i += 128) {
        int o = i / 576, ck = i % 576;
        s_w[ck * 20 + o] = ow[i];
    }
    __syncthreads();

    int p = blockIdx.x * 128 + tid;
    int b = p / HW;
    int pix = p % HW;
    int y = pix / Ww, x = pix % Ww;

    int  idx9[9]; bool ok9[9];
#pragma unroll
    for (int ky = 0; ky < 3; ky++)
#pragma unroll
        for (int kx = 0; kx < 3; kx++) {
            int yy = y + ky - 1, xx = x + kx - 1;
            bool ok = (yy >= 0) && (yy < Hh) && (xx >= 0) && (xx < Ww);
            ok9[ky * 3 + kx] = ok;
            idx9[ky * 3 + kx] = (ok ? yy : 0) * Ww + (ok ? xx : 0);
        }

    float acc[18];
#pragma unroll
    for (int o = 0; o < 18; o++) acc[o] = 0.f;

    const float* xb = ref + b * IMG;
    for (int c = 0; c < Cc; c++) {
        const float* xc = xb + c * HW;
#pragma unroll
        for (int k = 0; k < 9; k++) {
            float v = ok9[k] ? __ldg(xc + idx9[k]) : 0.f;
            int base = (c * 9 + k) * 20;
            float4 w0 = *(const float4*)&s_w[base];
            float4 w1 = *(const float4*)&s_w[base + 4];
            float4 w2 = *(const float4*)&s_w[base + 8];
            float4 w3 = *(const float4*)&s_w[base + 12];
            float  wa = s_w[base + 16];
            float  wb = s_w[base + 17];
            acc[0]  += v * w0.x;  acc[1]  += v * w0.y;  acc[2]  += v * w0.z;  acc[3]  += v * w0.w;
            acc[4]  += v * w1.x;  acc[5]  += v * w1.y;  acc[6]  += v * w1.z;  acc[7]  += v * w1.w;
            acc[8]  += v * w2.x;  acc[9]  += v * w2.y;  acc[10] += v * w2.z;  acc[11] += v * w2.w;
            acc[12] += v * w3.x;  acc[13] += v * w3.y;  acc[14] += v * w3.z;  acc[15] += v * w3.w;
            acc[16] += v * wa;    acc[17] += v * wb;
        }
    }

#pragma unroll
    for (int k = 0; k < 9; k++) {
        float offy = acc[2 * k]     + __ldg(ob + 2 * k);
        float offx = acc[2 * k + 1] + __ldg(ob + 2 * k + 1);
        float py = (float)(y - 1 + k / 3) + offy;
        float px = (float)(x - 1 + k % 3) + offx;
        float fy = floorf(py), fx = floorf(px);
        int y0 = (int)fy, x0 = (int)fx;
        float dy = py - fy, dx = px - fx;
        float wv[4]; int iv[4];
#pragma unroll
        for (int t = 0; t < 4; t++) {
            int yt = y0 + (t >> 1);
            int xt = x0 + (t & 1);
            float wt = ((t >> 1) ? dy : (1.f - dy)) * ((t & 1) ? dx : (1.f - dx));
            bool valid = (yt >= 0) && (yt < Hh) && (xt >= 0) && (xt < Ww);
            int yc = yt < 0 ? 0 : (yt > Hh - 1 ? Hh - 1 : yt);
            int xc = xt < 0 ? 0 : (xt > Ww - 1 ? Ww - 1 : xt);
            wv[t] = valid ? wt : 0.f;
            iv[t] = yc * Ww + xc;
        }
        int mo = (b * 9 + k) * HW + pix;
        mw[mo] = make_float4(wv[0], wv[1], wv[2], wv[3]);
        mi[mo] = make_int4(iv[0], iv[1], iv[2], iv[3]);
    }
}

// ---------------------------------------------------------------------------
// Kernel 3: weight prep -> fp16 B tiles, XOR-swizzled [n][k] layout
// ---------------------------------------------------------------------------
__global__ void wprep_kernel(const float* __restrict__ dw,
                             __half* __restrict__ wh) {
    int i = blockIdx.x * blockDim.x + threadIdx.x;
    if (i >= NCH * 64 * 64) return;
    int c  = i & 63;
    int o  = (i >> 6) & 63;
    int ch = i >> 12;
    int k  = ch / 3;
    int cg = (ch % 3) * 64 + c;
    float v = __ldg(dw + o * (CIN3 * 9) + cg * 9 + k);
    int elem = o * 64 + (((c >> 3) ^ (o & 7)) << 3) + (c & 7);
    wh[ch * 4096 + elem] = __float2half_rn(v);
}

// ---------------------------------------------------------------------------
// Kernel 4: deformable conv, mma.sync fp16 single-term A_hi x B_hi.
// Double-buffered; build quarters interleaved into the 4 GEMM k-steps.
// Per buffer (24KB): A_hi@0 16K | B_hi@16K 8K
// ---------------------------------------------------------------------------
#define SM_BUF   24576
#define SM_AHOF  0
#define SM_BHOF  16384
#define SM_TOTAL (2 * SM_BUF)

__global__ __launch_bounds__(256, 2) void deform_kernel(
        const float* __restrict__ ref, const float* __restrict__ dist,
        const float* __restrict__ diffp,
        const float4* __restrict__ mw, const int4* __restrict__ mi,
        const __half* __restrict__ wh,
        const float* __restrict__ db, float* __restrict__ out) {
    extern __shared__ char smem[];
    uint32_t sb = smem_to_u32(smem);

    int tid  = threadIdx.x;
    int lane = tid & 31;
    int warp = tid >> 5;
    int b    = blockIdx.x / 72;
    int pix0 = (blockIdx.x % 72) * 128;

    int p     = tid & 127;
    int chalf = tid >> 7;
    uint32_t a_sts = (uint32_t)p * 128;

    int m0 = (warp & 3) * 32;
    int n0 = (warp >> 2) * 32;

    const float* srcs[3];
    srcs[0] = ref   + b * IMG;
    srcs[1] = dist  + b * IMG;
    srcs[2] = diffp + b * IMG;

    float acc[2][4][4];
#pragma unroll
    for (int i = 0; i < 2; i++)
#pragma unroll
        for (int j = 0; j < 4; j++)
#pragma unroll
            for (int q = 0; q < 4; q++) acc[i][j][q] = 0.f;

    uint32_t a_m  = lane & 15;
    uint32_t a_kc = lane >> 4;
    uint32_t b_n  = ((lane >> 4) << 3) + (lane & 7);
    uint32_t b_kc = (lane >> 3) & 1;

    int bcp0 = tid;

    // build one quarter (8 channels) of chunk ch
    auto build_q = [&](int ch, int q, const float4& wgt, const int4& idx,
                       const float* src) {
        char* bufc = smem + (ch & 1) * SM_BUF;
        float v[8];
#pragma unroll
        for (int j = 0; j < 8; j++) {
            const float* pl = src + (size_t)(q * 8 + j) * HW;
            v[j] = wgt.x * __ldg(pl + idx.x) + wgt.y * __ldg(pl + idx.y)
                 + wgt.z * __ldg(pl + idx.z) + wgt.w * __ldg(pl + idx.w);
        }
        uint32_t hp[4];
#pragma unroll
        for (int jj = 0; jj < 4; jj++) {
            __half2 hb = __float22half2_rn(make_float2(v[2 * jj], v[2 * jj + 1]));
            hp[jj] = *(uint32_t*)&hb;
        }
        int kc = chalf * 4 + q;
        uint32_t off = a_sts + (uint32_t)((kc ^ (p & 7)) << 4);
        *(uint4*)(bufc + SM_AHOF + off) = make_uint4(hp[0], hp[1], hp[2], hp[3]);
    };

    auto stage_B = [&](int ch) {
        uint32_t bufb = sb + (ch & 1) * SM_BUF;
        const char* gh = (const char*)(wh + ch * 4096);
        cp_async16(bufb + SM_BHOF + bcp0 * 16, gh + bcp0 * 16);
        cp_async16(bufb + SM_BHOF + (bcp0 + 256) * 16, gh + (bcp0 + 256) * 16);
        CP_COMMIT();
    };

    // prologue: chunk 0
    stage_B(0);
    {
        float4 wgt = __ldg(mw + (b * 9 + 0) * HW + pix0 + p);
        int4   idx = __ldg(mi + (b * 9 + 0) * HW + pix0 + p);
        const float* src = srcs[0] + (size_t)(chalf * 32) * HW;
#pragma unroll
        for (int q = 0; q < 4; q++) build_q(0, q, wgt, idx, src);
    }
    CP_WAIT0();
    __syncthreads();

    for (int ch = 0; ch < NCH; ch++) {
        int nxt = ch + 1;
        bool has_nxt = (nxt < NCH);
        if (has_nxt) stage_B(nxt);

        float4 nwgt = make_float4(0, 0, 0, 0);
        int4   nidx = make_int4(0, 0, 0, 0);
        const float* nsrc = srcs[0];
        if (has_nxt) {
            int k = nxt / 3, cbl = nxt - 3 * k;
            nwgt = __ldg(mw + (b * 9 + k) * HW + pix0 + p);
            nidx = __ldg(mi + (b * 9 + k) * HW + pix0 + p);
            nsrc = srcs[cbl] + (size_t)(chalf * 32) * HW;
        }

        uint32_t bufb = sb + (ch & 1) * SM_BUF;
#pragma unroll
        for (int ks = 0; ks < 4; ks++) {
            uint32_t ah[2][4], bh[2][4];
#pragma unroll
            for (int mi_ = 0; mi_ < 2; mi_++) {
                uint32_t row = m0 + mi_ * 16 + a_m;
                uint32_t aoff = row * 128 + ((((ks << 1) + a_kc) ^ (row & 7)) << 4);
                ldsm_x4(ah[mi_], bufb + SM_AHOF + aoff);
            }
#pragma unroll
            for (int g = 0; g < 2; g++) {
                uint32_t n  = n0 + g * 16 + b_n;
                uint32_t kc = (ks << 1) + b_kc;
                uint32_t boff = n * 128 + ((kc ^ (n & 7)) << 4);
                ldsm_x4(bh[g], bufb + SM_BHOF + boff);
            }
#pragma unroll
            for (int mi_ = 0; mi_ < 2; mi_++)
#pragma unroll
                for (int g = 0; g < 2; g++)
#pragma unroll
                    for (int s = 0; s < 2; s++) {
                        int ni = g * 2 + s;
                        mma_f16(acc[mi_][ni], ah[mi_], bh[g][2 * s], bh[g][2 * s + 1]);
                    }
            if (has_nxt) build_q(nxt, ks, nwgt, nidx, nsrc);
        }

        CP_WAIT0();
        __syncthreads();
    }

    // epilogue: bias + relu
    int r  = lane >> 2;
    int cp = (lane & 3) * 2;
#pragma unroll
    for (int mi_ = 0; mi_ < 2; mi_++) {
        int pixb = pix0 + m0 + mi_ * 16 + r;
#pragma unroll
        for (int ni = 0; ni < 4; ni++) {
            int o = n0 + ni * 8 + cp;
            float b0v = __ldg(db + o);
            float b1v = __ldg(db + o + 1);
            float* o0 = out + (size_t)(b * Oo + o) * HW;
            float* o1 = out + (size_t)(b * Oo + o + 1) * HW;
            float v;
            v = acc[mi_][ni][0] + b0v; o0[pixb]     = v > 0.f ? v : 0.f;
            v = acc[mi_][ni][1] + b1v; o1[pixb]     = v > 0.f ? v : 0.f;
            v = acc[mi_][ni][2] + b0v; o0[pixb + 8] = v > 0.f ? v : 0.f;
            v = acc[mi_][ni][3] + b1v; o1[pixb + 8] = v > 0.f ? v : 0.f;
        }
    }
}

// ---------------------------------------------------------------------------
extern "C" void kernel_launch(void* const* d_in, const int* in_sizes, int n_in,
                              void* d_out, int out_size) {
    const float* ref  = (const float*)d_in[0];
    const float* dist = (const float*)d_in[1];
    const float* ow   = (const float*)d_in[2];
    const float* ob   = (const float*)d_in[3];
    const float* dw   = (const float*)d_in[4];
    const float* db   = (const float*)d_in[5];
    float* out = (float*)d_out;
    float* out_feat = out;
    float* out_diff = out + Bb * IMG;

    float4* mw;  cudaGetSymbolAddress((void**)&mw, g_mw);
    int4*   mi;  cudaGetSymbolAddress((void**)&mi, g_mi);
    __half* wh;  cudaGetSymbolAddress((void**)&wh, g_wh);

    cudaFuncSetAttribute(deform_kernel,
                         cudaFuncAttributeMaxDynamicSharedMemorySize, SM_TOTAL);

    diff_kernel<<<(Bb * IMG + 255) / 256, 256>>>(ref, dist, out_diff);
    offset_meta_kernel<<<NPIX / 128, 128>>>(ref, ow, ob, mw, mi);
    wprep_kernel<<<(NCH * 64 * 64 + 255) / 256, 256>>>(dw, wh);
    deform_kernel<<<NPIX / 128, 256, SM_TOTAL>>>(ref, dist, out_diff,
                                                 mw, mi, wh, db, out_feat);
}

// round 10
// speedup vs baseline: 1.4885x; 1.0994x over previous
#include <cuda_runtime.h>
#include <cuda_fp16.h>
#include <math.h>
#include <stdint.h>

// Problem constants
#define Bb   4
#define Cc   64
#define Hh   96
#define Ww   96
#define HW   (Hh*Ww)            // 9216
#define Oo   64
#define CIN3 (3*Cc)             // 192
#define IMG  (Cc*HW)            // 589824
#define NPIX (Bb*HW)            // 36864
#define NCH  27                 // K chunks of 64: K = k*192 + c (k-major)
#define NTOT (Bb*CIN3*HW)       // 7077888 elements of packed input
#define XPAD 128                // margin for masked OOB pair reads

// Scratch
__device__ float4 g_mw[Bb * 9 * HW];
__device__ int    g_me[Bb * 9 * HW];           // pair-base element index e0
__device__ __half g_xn_raw[NTOT + 2 * XPAD];   // fp16 NCHW (ref|dist|diff)
__device__ __half g_xs_raw[NTOT + 2 * XPAD];   // shifted by +1 element
__device__ __half g_wh[NCH * 64 * 64];         // B tiles fp16 (pre-swizzled)

// ---------------- helpers ----------------
__device__ __forceinline__ uint32_t smem_to_u32(const void* p) {
    uint32_t a;
    asm("{ .reg .u64 t; cvta.to.shared.u64 t, %1; cvt.u32.u64 %0, t; }"
        : "=r"(a) : "l"(p));
    return a;
}
__device__ __forceinline__ void ldsm_x4(uint32_t* r, uint32_t addr) {
    asm volatile("ldmatrix.sync.aligned.m8n8.x4.shared.b16 {%0,%1,%2,%3}, [%4];"
        : "=r"(r[0]), "=r"(r[1]), "=r"(r[2]), "=r"(r[3]) : "r"(addr));
}
__device__ __forceinline__ void mma_f16(float* d, const uint32_t* a,
                                        uint32_t b0, uint32_t b1) {
    asm volatile("mma.sync.aligned.m16n8k16.row.col.f32.f16.f16.f32 "
        "{%0,%1,%2,%3}, {%4,%5,%6,%7}, {%8,%9}, {%0,%1,%2,%3};"
        : "+f"(d[0]), "+f"(d[1]), "+f"(d[2]), "+f"(d[3])
        : "r"(a[0]), "r"(a[1]), "r"(a[2]), "r"(a[3]), "r"(b0), "r"(b1));
}
__device__ __forceinline__ void cp_async16(uint32_t smem_addr, const void* gptr) {
    asm volatile("cp.async.cg.shared.global [%0], [%1], 16;"
        :: "r"(smem_addr), "l"(gptr));
}
#define CP_COMMIT() asm volatile("cp.async.commit_group;" ::: "memory")
#define CP_WAIT0()  asm volatile("cp.async.wait_group 0;" ::: "memory")

// ---------------------------------------------------------------------------
// Kernel 1: diff + fp16 NCHW repack (normal + shifted-by-1 copies)
// element i: b = i/(CIN3*HW), c = (i/HW)%CIN3, e = i%HW
// ---------------------------------------------------------------------------
__global__ void repack_kernel(const float* __restrict__ ref,
                              const float* __restrict__ dist,
                              float* __restrict__ out_diff,
                              __half* __restrict__ xn,    // +XPAD base
                              __half* __restrict__ xs) {  // +XPAD base
    int i = blockIdx.x * blockDim.x + threadIdx.x;
    if (i >= NTOT) return;
    int b = i / (CIN3 * HW);
    int r = i - b * (CIN3 * HW);
    int c = r / HW;
    int e = r - c * HW;
    float v;
    if (c < Cc) {
        v = __ldg(ref + (b * Cc + c) * HW + e);
    } else if (c < 2 * Cc) {
        v = __ldg(dist + (b * Cc + (c - Cc)) * HW + e);
    } else {
        int cc = c - 2 * Cc;
        float rr = __ldg(ref  + (b * Cc + cc) * HW + e);
        float dd = __ldg(dist + (b * Cc + cc) * HW + e);
        v = (rr - dd) * (rr - dd);
        out_diff[(b * Cc + cc) * HW + e] = v;
    }
    __half h = __float2half_rn(v);
    xn[i] = h;
    if (i > 0) xs[i - 1] = h;
}

// ---------------------------------------------------------------------------
// Kernel 2: offset conv3x3 (Cin=64 -> 18) + fused bilinear meta (pair-based)
// ---------------------------------------------------------------------------
__global__ __launch_bounds__(128) void offset_meta_kernel(
        const float* __restrict__ ref,
        const float* __restrict__ ow, const float* __restrict__ ob,
        float4* __restrict__ mw, int* __restrict__ me) {
    __shared__ __align__(16) float s_w[576 * 20];
    int tid = threadIdx.x;
    for (int i = tid; i < 18 * 576; i += 128) {
        int o = i / 576, ck = i % 576;
        s_w[ck * 20 + o] = ow[i];
    }
    __syncthreads();

    int p = blockIdx.x * 128 + tid;
    int b = p / HW;
    int pix = p % HW;
    int y = pix / Ww, x = pix % Ww;

    int  idx9[9]; bool ok9[9];
#pragma unroll
    for (int ky = 0; ky < 3; ky++)
#pragma unroll
        for (int kx = 0; kx < 3; kx++) {
            int yy = y + ky - 1, xx = x + kx - 1;
            bool ok = (yy >= 0) && (yy < Hh) && (xx >= 0) && (xx < Ww);
            ok9[ky * 3 + kx] = ok;
            idx9[ky * 3 + kx] = (ok ? yy : 0) * Ww + (ok ? xx : 0);
        }

    float acc[18];
#pragma unroll
    for (int o = 0; o < 18; o++) acc[o] = 0.f;

    const float* xb = ref + b * IMG;
    for (int c = 0; c < Cc; c++) {
        const float* xc = xb + c * HW;
#pragma unroll
        for (int k = 0; k < 9; k++) {
            float v = ok9[k] ? __ldg(xc + idx9[k]) : 0.f;
            int base = (c * 9 + k) * 20;
            float4 w0 = *(const float4*)&s_w[base];
            float4 w1 = *(const float4*)&s_w[base + 4];
            float4 w2 = *(const float4*)&s_w[base + 8];
            float4 w3 = *(const float4*)&s_w[base + 12];
            float  wa = s_w[base + 16];
            float  wb = s_w[base + 17];
            acc[0]  += v * w0.x;  acc[1]  += v * w0.y;  acc[2]  += v * w0.z;  acc[3]  += v * w0.w;
            acc[4]  += v * w1.x;  acc[5]  += v * w1.y;  acc[6]  += v * w1.z;  acc[7]  += v * w1.w;
            acc[8]  += v * w2.x;  acc[9]  += v * w2.y;  acc[10] += v * w2.z;  acc[11] += v * w2.w;
            acc[12] += v * w3.x;  acc[13] += v * w3.y;  acc[14] += v * w3.z;  acc[15] += v * w3.w;
            acc[16] += v * wa;    acc[17] += v * wb;
        }
    }

#pragma unroll
    for (int k = 0; k < 9; k++) {
        float offy = acc[2 * k]     + __ldg(ob + 2 * k);
        float offx = acc[2 * k + 1] + __ldg(ob + 2 * k + 1);
        float py = (float)(y - 1 + k / 3) + offy;
        float px = (float)(x - 1 + k % 3) + offx;
        float fy = floorf(py), fx = floorf(px);
        int y0 = (int)fy, x0 = (int)fx;
        float dy = py - fy, dx = px - fx;
        // exact reference weights with validity masking
        float wv[4];
#pragma unroll
        for (int t = 0; t < 4; t++) {
            int yt = y0 + (t >> 1);
            int xt = x0 + (t & 1);
            float wt = ((t >> 1) ? dy : (1.f - dy)) * ((t & 1) ? dx : (1.f - dx));
            bool valid = (yt >= 0) && (yt < Hh) && (xt >= 0) && (xt < Ww);
            wv[t] = valid ? wt : 0.f;
        }
        // pair base address (clamped for safety; weights mask garbage)
        int y0c = y0 < -1 ? -1 : (y0 > Hh ? Hh : y0);
        int x0c = x0 < -1 ? -1 : (x0 > Ww ? Ww : x0);
        int e0 = y0c * Ww + x0c;
        int mo = (b * 9 + k) * HW + pix;
        mw[mo] = make_float4(wv[0], wv[1], wv[2], wv[3]);
        me[mo] = e0;
    }
}

// ---------------------------------------------------------------------------
// Kernel 3: weight prep -> fp16 B tiles, XOR-swizzled [n][k] layout
// ---------------------------------------------------------------------------
__global__ void wprep_kernel(const float* __restrict__ dw,
                             __half* __restrict__ wh) {
    int i = blockIdx.x * blockDim.x + threadIdx.x;
    if (i >= NCH * 64 * 64) return;
    int c  = i & 63;
    int o  = (i >> 6) & 63;
    int ch = i >> 12;
    int k  = ch / 3;
    int cg = (ch % 3) * 64 + c;
    float v = __ldg(dw + o * (CIN3 * 9) + cg * 9 + k);
    int elem = o * 64 + (((c >> 3) ^ (o & 7)) << 3) + (c & 7);
    wh[ch * 4096 + elem] = __float2half_rn(v);
}

// ---------------------------------------------------------------------------
// Kernel 4: deformable conv, mma.sync fp16 A_hi x B_hi, double-buffered.
// Gather: fp16 paired-tap loads (half2 covers both x taps; parity picks
// normal vs shifted copy). Interp in half2 HFMA.
// Per buffer (24KB): A_hi@0 16K | B_hi@16K 8K
// ---------------------------------------------------------------------------
#define SM_BUF   24576
#define SM_AHOF  0
#define SM_BHOF  16384
#define SM_TOTAL (2 * SM_BUF)

__global__ __launch_bounds__(256, 2) void deform_kernel(
        const __half* __restrict__ xn, const __half* __restrict__ xs,
        const float4* __restrict__ mw, const int* __restrict__ me,
        const __half* __restrict__ wh,
        const float* __restrict__ db, float* __restrict__ out) {
    extern __shared__ char smem[];
    uint32_t sb = smem_to_u32(smem);

    int tid  = threadIdx.x;
    int lane = tid & 31;
    int warp = tid >> 5;
    int b    = blockIdx.x / 72;
    int pix0 = (blockIdx.x % 72) * 128;

    int p     = tid & 127;
    int chalf = tid >> 7;
    uint32_t a_sts = (uint32_t)p * 128;

    int m0 = (warp & 3) * 32;
    int n0 = (warp >> 2) * 32;

    float acc[2][4][4];
#pragma unroll
    for (int i = 0; i < 2; i++)
#pragma unroll
        for (int j = 0; j < 4; j++)
#pragma unroll
            for (int q = 0; q < 4; q++) acc[i][j][q] = 0.f;

    uint32_t a_m  = lane & 15;
    uint32_t a_kc = lane >> 4;
    uint32_t b_n  = ((lane >> 4) << 3) + (lane & 7);
    uint32_t b_kc = (lane >> 3) & 1;

    int bcp0 = tid;

    // per-thread channel base within batch (chalf half of each 64-chunk)
    // plane index (in half2 units) for channel c of block cbl:
    //   ((b*CIN3 + cbl*64 + chalf*32 + j)*HW + e0pair) / 2
    // HW even -> = (b*CIN3 + ...)*4608 + h2base

    // build one quarter (8 channels) of chunk ch
    auto build_q = [&](int ch, int q, __half2 wtop, __half2 wbot,
                       const __half2* srcp) {
        char* bufc = smem + (ch & 1) * SM_BUF;
        __half v[8];
#pragma unroll
        for (int j = 0; j < 8; j++) {
            const __half2* pl = srcp + (q * 8 + j) * (HW / 2);
            __half2 a  = __ldg(pl);
            __half2 bb = __ldg(pl + (Ww / 2));
            __half2 t  = __hfma2(wbot, bb, __hmul2(wtop, a));
            v[j] = __hadd(__low2half(t), __high2half(t));
        }
        uint32_t hp[4];
#pragma unroll
        for (int jj = 0; jj < 4; jj++) {
            __half2 hb = __halves2half2(v[2 * jj], v[2 * jj + 1]);
            hp[jj] = *(uint32_t*)&hb;
        }
        int kc = chalf * 4 + q;
        uint32_t off = a_sts + (uint32_t)((kc ^ (p & 7)) << 4);
        *(uint4*)(bufc + SM_AHOF + off) = make_uint4(hp[0], hp[1], hp[2], hp[3]);
    };

    // per-chunk meta -> (wtop, wbot, srcp)
    auto chunk_meta = [&](int ch, __half2& wtop, __half2& wbot,
                          const __half2*& srcp) {
        int k   = ch / 3;
        int cbl = ch - 3 * k;
        float4 w = __ldg(mw + (b * 9 + k) * HW + pix0 + p);
        int   e0 = __ldg(me + (b * 9 + k) * HW + pix0 + p);
        wtop = __floats2half2_rn(w.x, w.y);
        wbot = __floats2half2_rn(w.z, w.w);
        int sel = e0 & 1;
        int h2base = (e0 - sel) >> 1;
        const __half* base = sel ? xs : xn;
        srcp = (const __half2*)base
             + (size_t)(b * CIN3 + cbl * 64 + chalf * 32) * (HW / 2)
             + h2base;
    };

    auto stage_B = [&](int ch) {
        uint32_t bufb = sb + (ch & 1) * SM_BUF;
        const char* gh = (const char*)(wh + ch * 4096);
        cp_async16(bufb + SM_BHOF + bcp0 * 16, gh + bcp0 * 16);
        cp_async16(bufb + SM_BHOF + (bcp0 + 256) * 16, gh + (bcp0 + 256) * 16);
        CP_COMMIT();
    };

    // prologue: chunk 0
    stage_B(0);
    {
        __half2 wtop, wbot; const __half2* srcp;
        chunk_meta(0, wtop, wbot, srcp);
#pragma unroll
        for (int q = 0; q < 4; q++) build_q(0, q, wtop, wbot, srcp);
    }
    CP_WAIT0();
    __syncthreads();

    for (int ch = 0; ch < NCH; ch++) {
        int nxt = ch + 1;
        bool has_nxt = (nxt < NCH);
        if (has_nxt) stage_B(nxt);

        __half2 nwt = __float2half2_rn(0.f), nwb = __float2half2_rn(0.f);
        const __half2* nsrc = (const __half2*)xn;
        if (has_nxt) chunk_meta(nxt, nwt, nwb, nsrc);

        uint32_t bufb = sb + (ch & 1) * SM_BUF;
#pragma unroll
        for (int ks = 0; ks < 4; ks++) {
            uint32_t ah[2][4], bh[2][4];
#pragma unroll
            for (int mi_ = 0; mi_ < 2; mi_++) {
                uint32_t row = m0 + mi_ * 16 + a_m;
                uint32_t aoff = row * 128 + ((((ks << 1) + a_kc) ^ (row & 7)) << 4);
                ldsm_x4(ah[mi_], bufb + SM_AHOF + aoff);
            }
#pragma unroll
            for (int g = 0; g < 2; g++) {
                uint32_t n  = n0 + g * 16 + b_n;
                uint32_t kc = (ks << 1) + b_kc;
                uint32_t boff = n * 128 + ((kc ^ (n & 7)) << 4);
                ldsm_x4(bh[g], bufb + SM_BHOF + boff);
            }
#pragma unroll
            for (int mi_ = 0; mi_ < 2; mi_++)
#pragma unroll
                for (int g = 0; g < 2; g++)
#pragma unroll
                    for (int s = 0; s < 2; s++) {
                        int ni = g * 2 + s;
                        mma_f16(acc[mi_][ni], ah[mi_], bh[g][2 * s], bh[g][2 * s + 1]);
                    }
            if (has_nxt) build_q(nxt, ks, nwt, nwb, nsrc);
        }

        CP_WAIT0();
        __syncthreads();
    }

    // epilogue: bias + relu
    int r  = lane >> 2;
    int cp = (lane & 3) * 2;
#pragma unroll
    for (int mi_ = 0; mi_ < 2; mi_++) {
        int pixb = pix0 + m0 + mi_ * 16 + r;
#pragma unroll
        for (int ni = 0; ni < 4; ni++) {
            int o = n0 + ni * 8 + cp;
            float b0v = __ldg(db + o);
            float b1v = __ldg(db + o + 1);
            float* o0 = out + (size_t)(b * Oo + o) * HW;
            float* o1 = out + (size_t)(b * Oo + o + 1) * HW;
            float v;
            v = acc[mi_][ni][0] + b0v; o0[pixb]     = v > 0.f ? v : 0.f;
            v = acc[mi_][ni][1] + b1v; o1[pixb]     = v > 0.f ? v : 0.f;
            v = acc[mi_][ni][2] + b0v; o0[pixb + 8] = v > 0.f ? v : 0.f;
            v = acc[mi_][ni][3] + b1v; o1[pixb + 8] = v > 0.f ? v : 0.f;
        }
    }
}

// ---------------------------------------------------------------------------
extern "C" void kernel_launch(void* const* d_in, const int* in_sizes, int n_in,
                              void* d_out, int out_size) {
    const float* ref  = (const float*)d_in[0];
    const float* dist = (const float*)d_in[1];
    const float* ow   = (const float*)d_in[2];
    const float* ob   = (const float*)d_in[3];
    const float* dw   = (const float*)d_in[4];
    const float* db   = (const float*)d_in[5];
    float* out = (float*)d_out;
    float* out_feat = out;
    float* out_diff = out + Bb * IMG;

    float4* mw;  cudaGetSymbolAddress((void**)&mw, g_mw);
    int*    me;  cudaGetSymbolAddress((void**)&me, g_me);
    __half* xnr; cudaGetSymbolAddress((void**)&xnr, g_xn_raw);
    __half* xsr; cudaGetSymbolAddress((void**)&xsr, g_xs_raw);
    __half* wh;  cudaGetSymbolAddress((void**)&wh, g_wh);
    __half* xn = xnr + XPAD;
    __half* xs = xsr + XPAD;

    cudaFuncSetAttribute(deform_kernel,
                         cudaFuncAttributeMaxDynamicSharedMemorySize, SM_TOTAL);

    repack_kernel<<<(NTOT + 255) / 256, 256>>>(ref, dist, out_diff, xn, xs);
    offset_meta_kernel<<<NPIX / 128, 128>>>(ref, ow, ob, mw, me);
    wprep_kernel<<<(NCH * 64 * 64 + 255) / 256, 256>>>(dw, wh);
    deform_kernel<<<NPIX / 128, 256, SM_TOTAL>>>(xn, xs, mw, me, wh, db, out_feat);
}